// round 15
// baseline (speedup 1.0000x reference)
#include <cuda_runtime.h>

// Problem constants
#define KB 32
#define KN 25200
#define KM 200
#define KC 80
#define KEPS 1e-7f

#define TPB 256
#define GRID 592                       /* 148 SMs x 4 blocks = one wave */

#define POS (KB * KM)                  /* 6400  positive items    */
#define NEGF ((KN - KM) / 4)           /* 6250  float4 per batch  */
#define NEG4 (KB * NEGF)               /* 200000 float4 chunks    */
#define NEG_CNT (KB * (KN - KM))       /* 800000 neg elements     */
#define NTHREADS (GRID * TPB)          /* 151552                  */
#define NWARPS (NTHREADS / 32)         /* 4736                    */

// Persistent device accumulators (zeroed at load; finalizing block resets
// them every launch so graph replays are clean). No device allocation.
__device__ double g_acc[4];            // bbox, obj_pos, obj_neg, cls
__device__ unsigned int g_done;

__device__ __forceinline__ float softplusf(float x) {
    // stable, MUFU-only: max(x,0) + log(1 + exp(-|x|))
    return fmaxf(x, 0.0f) + __logf(1.0f + __expf(-fabsf(x)));
}

__global__ __launch_bounds__(TPB, 4) void det_loss_kernel(
    const float* __restrict__ pred_bbox,   // (B, N, 4)
    const float* __restrict__ pred_obj,    // (B, N)
    const float* __restrict__ pred_cls,    // (B, N, C)
    const float* __restrict__ gt_boxes,    // (B, M, 4)
    const int*   __restrict__ gt_labels,   // (B, M)
    float* __restrict__ out)               // (4,)
{
    const int tid  = threadIdx.x;
    const int gtid = blockIdx.x * TPB + tid;
    const int lane = tid & 31;

    float s_bbox = 0.0f, s_pos = 0.0f, s_neg = 0.0f, s_cls = 0.0f;

    // ---------------- negative obj region: softplus(x), 2 predicated loads -
    // NEG4 = 200000 < 2 * NTHREADS, so at most two chunks per thread.
    {
        float4 o0 = make_float4(0.f, 0.f, 0.f, 0.f);
        float4 o1 = make_float4(0.f, 0.f, 0.f, 0.f);
        const bool v0 = gtid < NEG4;
        const bool v1 = gtid + NTHREADS < NEG4;
        if (v0) {
            int i = gtid;
            int b = i / NEGF, q = i - b * NEGF;
            o0 = *reinterpret_cast<const float4*>(
                pred_obj + (size_t)b * KN + KM + 4 * (size_t)q);
        }
        if (v1) {
            int i = gtid + NTHREADS;
            int b = i / NEGF, q = i - b * NEGF;
            o1 = *reinterpret_cast<const float4*>(
                pred_obj + (size_t)b * KN + KM + 4 * (size_t)q);
        }
        if (v0) s_neg += softplusf(o0.x) + softplusf(o0.y)
                       + softplusf(o0.z) + softplusf(o0.w);
        if (v1) s_neg += softplusf(o1.x) + softplusf(o1.y)
                       + softplusf(o1.z) + softplusf(o1.w);
    }

    // ---------------- positive items: GIoU + obj_pos (thread-per-item) -----
    if (gtid < POS) {
        const int i = gtid;
        const int b = i / KM;
        const int m = i - b * KM;
        const size_t pidx = (size_t)b * KN + m;

        float4 pb = *reinterpret_cast<const float4*>(pred_bbox + pidx * 4);
        float4 tb = *reinterpret_cast<const float4*>(gt_boxes + (size_t)i * 4);

        float px1 = pb.x - pb.z * 0.5f, py1 = pb.y - pb.w * 0.5f;
        float px2 = pb.x + pb.z * 0.5f, py2 = pb.y + pb.w * 0.5f;
        float tx1 = tb.x - tb.z * 0.5f, ty1 = tb.y - tb.w * 0.5f;
        float tx2 = tb.x + tb.z * 0.5f, ty2 = tb.y + tb.w * 0.5f;

        float ix1 = fmaxf(px1, tx1), iy1 = fmaxf(py1, ty1);
        float ix2 = fminf(px2, tx2), iy2 = fminf(py2, ty2);
        float inter = fmaxf(ix2 - ix1, 0.0f) * fmaxf(iy2 - iy1, 0.0f);
        float uni = (px2 - px1) * (py2 - py1)
                  + (tx2 - tx1) * (ty2 - ty1) - inter;
        float iou = inter / (uni + KEPS);

        float ex1 = fminf(px1, tx1), ey1 = fminf(py1, ty1);
        float ex2 = fmaxf(px2, tx2), ey2 = fmaxf(py2, ty2);
        float enclose = (ex2 - ex1) * (ey2 - ey1);
        s_bbox += 1.0f - (iou - (enclose - uni) / (enclose + KEPS));

        s_pos += softplusf(-pred_obj[pidx]);
    }

    // ---------------- class NLL: warp-per-item, coalesced ------------------
    // 6400 items over 4736 warps -> at most 2 items per warp (predicated,
    // whole warp takes the same branch).
    {
        const int gw = gtid >> 5;                 // global warp id
        #pragma unroll
        for (int it = 0; it < 2; ++it) {
            const int i = gw + it * NWARPS;
            if (i >= POS) break;
            const int b = i / KM;
            const int m = i - b * KM;
            const float* row = pred_cls + ((size_t)b * KN + m) * KC;

            float x0 = row[lane];
            float x1 = row[lane + 32];
            float x2 = (lane < 16) ? row[lane + 64] : -1e30f;

            float mx = fmaxf(fmaxf(x0, x1), x2);
            #pragma unroll
            for (int off = 16; off > 0; off >>= 1)
                mx = fmaxf(mx, __shfl_xor_sync(0xffffffffu, mx, off));

            float se = __expf(x0 - mx) + __expf(x1 - mx)
                     + ((lane < 16) ? __expf(x2 - mx) : 0.0f);
            #pragma unroll
            for (int off = 16; off > 0; off >>= 1)
                se += __shfl_xor_sync(0xffffffffu, se, off);

            if (lane == 0) {
                const int lbl = gt_labels[i];
                const float vl = row[lbl];        // L1/L2 hit (row just read)
                s_cls += mx + __logf(se) - vl;
            }
        }
    }

    // ---------------- reduction: warp -> block -> global -------------------
    #pragma unroll
    for (int off = 16; off > 0; off >>= 1) {
        s_bbox += __shfl_down_sync(0xffffffffu, s_bbox, off);
        s_pos  += __shfl_down_sync(0xffffffffu, s_pos,  off);
        s_neg  += __shfl_down_sync(0xffffffffu, s_neg,  off);
        s_cls  += __shfl_down_sync(0xffffffffu, s_cls,  off);
    }

    __shared__ float sh[4][TPB / 32];
    const int warp = tid >> 5;
    if (lane == 0) {
        sh[0][warp] = s_bbox;
        sh[1][warp] = s_pos;
        sh[2][warp] = s_neg;
        sh[3][warp] = s_cls;
    }
    __syncthreads();

    if (tid == 0) {
        double t0 = 0.0, t1 = 0.0, t2 = 0.0, t3 = 0.0;
        #pragma unroll
        for (int w = 0; w < TPB / 32; ++w) {
            t0 += (double)sh[0][w]; t1 += (double)sh[1][w];
            t2 += (double)sh[2][w]; t3 += (double)sh[3][w];
        }
        atomicAdd(&g_acc[0], t0);
        atomicAdd(&g_acc[1], t1);
        atomicAdd(&g_acc[2], t2);
        atomicAdd(&g_acc[3], t3);
        __threadfence();
        unsigned int old = atomicAdd(&g_done, 1u);
        if (old == gridDim.x - 1) {
            __threadfence();
            double bb = atomicAdd(&g_acc[0], 0.0);
            double po = atomicAdd(&g_acc[1], 0.0);
            double ne = atomicAdd(&g_acc[2], 0.0);
            double cl = atomicAdd(&g_acc[3], 0.0);

            double loss_bbox = bb / (double)POS * 5.0;            // LAMBDA_COORD
            double loss_obj  = po / (double)POS * 1.0             // LAMBDA_OBJ
                             + ne / (double)NEG_CNT * 0.5;        // LAMBDA_NOOBJ
            double loss_cls  = cl / (double)POS * 1.0;            // LAMBDA_CLS
            double total = loss_bbox + loss_obj + loss_cls;

            out[0] = (float)total;
            out[1] = (float)loss_bbox;
            out[2] = (float)loss_obj;
            out[3] = (float)loss_cls;

            // reset for next graph replay
            g_acc[0] = 0.0; g_acc[1] = 0.0; g_acc[2] = 0.0; g_acc[3] = 0.0;
            g_done = 0u;
            __threadfence();
        }
    }
}

extern "C" void kernel_launch(void* const* d_in, const int* in_sizes, int n_in,
                              void* d_out, int out_size) {
    const float* pred_bbox = (const float*)d_in[0];
    const float* pred_obj  = (const float*)d_in[1];
    const float* pred_cls  = (const float*)d_in[2];
    const float* gt_boxes  = (const float*)d_in[3];
    const int*   gt_labels = (const int*)d_in[4];
    float* out = (float*)d_out;

    det_loss_kernel<<<GRID, TPB>>>(pred_bbox, pred_obj, pred_cls,
                                   gt_boxes, gt_labels, out);
}

// round 16
// speedup vs baseline: 1.0173x; 1.0173x over previous
#include <cuda_runtime.h>

// Problem constants
#define KB 32
#define KN 25200
#define KM 200
#define KC 80
#define KEPS 1e-7f

#define TPB 256
#define GRID 592                       /* 148 SMs x 4 blocks = one wave */

#define POS (KB * KM)                  /* 6400  positive items    */
#define NEGF ((KN - KM) / 4)           /* 6250  float4 per batch  */
#define NEG4 (KB * NEGF)               /* 200000 float4 chunks    */
#define NEG_CNT (KB * (KN - KM))       /* 800000 neg elements     */
#define NTHREADS (GRID * TPB)          /* 151552                  */
#define NWARPS (NTHREADS / 32)         /* 4736                    */

// Persistent device accumulators (zeroed at load; finalizing block resets
// them every launch so graph replays are clean). No device allocation.
__device__ double g_acc[4];            // bbox, obj_pos, obj_neg, cls
__device__ unsigned int g_done;

__device__ __forceinline__ float softplusf(float x) {
    // stable, MUFU-only: max(x,0) + log(1 + exp(-|x|))
    return fmaxf(x, 0.0f) + __logf(1.0f + __expf(-fabsf(x)));
}

__global__ __launch_bounds__(TPB, 4) void det_loss_kernel(
    const float* __restrict__ pred_bbox,   // (B, N, 4)
    const float* __restrict__ pred_obj,    // (B, N)
    const float* __restrict__ pred_cls,    // (B, N, C)
    const float* __restrict__ gt_boxes,    // (B, M, 4)
    const int*   __restrict__ gt_labels,   // (B, M)
    float* __restrict__ out)               // (4,)
{
    const int tid  = threadIdx.x;
    const int gtid = blockIdx.x * TPB + tid;
    const int lane = tid & 31;

    float s_bbox = 0.0f, s_pos = 0.0f, s_neg = 0.0f, s_cls = 0.0f;

    // ---------------- negative obj region: softplus(x), 2 predicated loads -
    // NEG4 = 200000 < 2 * NTHREADS, so at most two chunks per thread.
    {
        float4 o0 = make_float4(0.f, 0.f, 0.f, 0.f);
        float4 o1 = make_float4(0.f, 0.f, 0.f, 0.f);
        const bool v0 = gtid < NEG4;
        const bool v1 = gtid + NTHREADS < NEG4;
        if (v0) {
            int i = gtid;
            int b = i / NEGF, q = i - b * NEGF;
            o0 = *reinterpret_cast<const float4*>(
                pred_obj + (size_t)b * KN + KM + 4 * (size_t)q);
        }
        if (v1) {
            int i = gtid + NTHREADS;
            int b = i / NEGF, q = i - b * NEGF;
            o1 = *reinterpret_cast<const float4*>(
                pred_obj + (size_t)b * KN + KM + 4 * (size_t)q);
        }
        if (v0) s_neg += softplusf(o0.x) + softplusf(o0.y)
                       + softplusf(o0.z) + softplusf(o0.w);
        if (v1) s_neg += softplusf(o1.x) + softplusf(o1.y)
                       + softplusf(o1.z) + softplusf(o1.w);
    }

    // ---------------- positive items: GIoU + obj_pos (thread-per-item) -----
    if (gtid < POS) {
        const int i = gtid;
        const int b = i / KM;
        const int m = i - b * KM;
        const size_t pidx = (size_t)b * KN + m;

        float4 pb = *reinterpret_cast<const float4*>(pred_bbox + pidx * 4);
        float4 tb = *reinterpret_cast<const float4*>(gt_boxes + (size_t)i * 4);

        float px1 = pb.x - pb.z * 0.5f, py1 = pb.y - pb.w * 0.5f;
        float px2 = pb.x + pb.z * 0.5f, py2 = pb.y + pb.w * 0.5f;
        float tx1 = tb.x - tb.z * 0.5f, ty1 = tb.y - tb.w * 0.5f;
        float tx2 = tb.x + tb.z * 0.5f, ty2 = tb.y + tb.w * 0.5f;

        float ix1 = fmaxf(px1, tx1), iy1 = fmaxf(py1, ty1);
        float ix2 = fminf(px2, tx2), iy2 = fminf(py2, ty2);
        float inter = fmaxf(ix2 - ix1, 0.0f) * fmaxf(iy2 - iy1, 0.0f);
        float uni = (px2 - px1) * (py2 - py1)
                  + (tx2 - tx1) * (ty2 - ty1) - inter;
        float iou = inter / (uni + KEPS);

        float ex1 = fminf(px1, tx1), ey1 = fminf(py1, ty1);
        float ex2 = fmaxf(px2, tx2), ey2 = fmaxf(py2, ty2);
        float enclose = (ex2 - ex1) * (ey2 - ey1);
        s_bbox += 1.0f - (iou - (enclose - uni) / (enclose + KEPS));

        s_pos += softplusf(-pred_obj[pidx]);
    }

    // ---------------- class NLL: warp-per-item, coalesced ------------------
    // 6400 items over 4736 warps -> at most 2 items per warp (predicated,
    // whole warp takes the same branch).
    {
        const int gw = gtid >> 5;                 // global warp id
        #pragma unroll
        for (int it = 0; it < 2; ++it) {
            const int i = gw + it * NWARPS;
            if (i >= POS) break;
            const int b = i / KM;
            const int m = i - b * KM;
            const float* row = pred_cls + ((size_t)b * KN + m) * KC;

            float x0 = row[lane];
            float x1 = row[lane + 32];
            float x2 = (lane < 16) ? row[lane + 64] : -1e30f;

            float mx = fmaxf(fmaxf(x0, x1), x2);
            #pragma unroll
            for (int off = 16; off > 0; off >>= 1)
                mx = fmaxf(mx, __shfl_xor_sync(0xffffffffu, mx, off));

            float se = __expf(x0 - mx) + __expf(x1 - mx)
                     + ((lane < 16) ? __expf(x2 - mx) : 0.0f);
            #pragma unroll
            for (int off = 16; off > 0; off >>= 1)
                se += __shfl_xor_sync(0xffffffffu, se, off);

            if (lane == 0) {
                const int lbl = gt_labels[i];
                const float vl = row[lbl];        // L1/L2 hit (row just read)
                s_cls += mx + __logf(se) - vl;
            }
        }
    }

    // ---------------- reduction: warp -> block -> global -------------------
    #pragma unroll
    for (int off = 16; off > 0; off >>= 1) {
        s_bbox += __shfl_down_sync(0xffffffffu, s_bbox, off);
        s_pos  += __shfl_down_sync(0xffffffffu, s_pos,  off);
        s_neg  += __shfl_down_sync(0xffffffffu, s_neg,  off);
        s_cls  += __shfl_down_sync(0xffffffffu, s_cls,  off);
    }

    __shared__ float sh[4][TPB / 32];
    const int warp = tid >> 5;
    if (lane == 0) {
        sh[0][warp] = s_bbox;
        sh[1][warp] = s_pos;
        sh[2][warp] = s_neg;
        sh[3][warp] = s_cls;
    }
    __syncthreads();

    if (tid == 0) {
        double t0 = 0.0, t1 = 0.0, t2 = 0.0, t3 = 0.0;
        #pragma unroll
        for (int w = 0; w < TPB / 32; ++w) {
            t0 += (double)sh[0][w]; t1 += (double)sh[1][w];
            t2 += (double)sh[2][w]; t3 += (double)sh[3][w];
        }
        atomicAdd(&g_acc[0], t0);
        atomicAdd(&g_acc[1], t1);
        atomicAdd(&g_acc[2], t2);
        atomicAdd(&g_acc[3], t3);
        __threadfence();
        unsigned int old = atomicAdd(&g_done, 1u);
        if (old == gridDim.x - 1) {
            __threadfence();
            double bb = atomicAdd(&g_acc[0], 0.0);
            double po = atomicAdd(&g_acc[1], 0.0);
            double ne = atomicAdd(&g_acc[2], 0.0);
            double cl = atomicAdd(&g_acc[3], 0.0);

            double loss_bbox = bb / (double)POS * 5.0;            // LAMBDA_COORD
            double loss_obj  = po / (double)POS * 1.0             // LAMBDA_OBJ
                             + ne / (double)NEG_CNT * 0.5;        // LAMBDA_NOOBJ
            double loss_cls  = cl / (double)POS * 1.0;            // LAMBDA_CLS
            double total = loss_bbox + loss_obj + loss_cls;

            out[0] = (float)total;
            out[1] = (float)loss_bbox;
            out[2] = (float)loss_obj;
            out[3] = (float)loss_cls;

            // reset for next graph replay
            g_acc[0] = 0.0; g_acc[1] = 0.0; g_acc[2] = 0.0; g_acc[3] = 0.0;
            g_done = 0u;
            __threadfence();
        }
    }
}

extern "C" void kernel_launch(void* const* d_in, const int* in_sizes, int n_in,
                              void* d_out, int out_size) {
    const float* pred_bbox = (const float*)d_in[0];
    const float* pred_obj  = (const float*)d_in[1];
    const float* pred_cls  = (const float*)d_in[2];
    const float* gt_boxes  = (const float*)d_in[3];
    const int*   gt_labels = (const int*)d_in[4];
    float* out = (float*)d_out;

    det_loss_kernel<<<GRID, TPB>>>(pred_bbox, pred_obj, pred_cls,
                                   gt_boxes, gt_labels, out);
}